// round 16
// baseline (speedup 1.0000x reference)
#include <cuda_runtime.h>
#include <math.h>

#define NG     320
#define NS1    (NG*NG)
#define NSHOT  2
#define NSRC   8
#define NREC   96
#define NT     160
#define PML_W  20
#define NBLK   256          // 128 tiles x 2 shots
#define TPB    544          // 17 warps: core 0-399, ring 400-527, pollers 528-535
#define TILE_R 20
#define TILE_C 40
#define TCB    8
#define TRB    16
#define EXT_R  24
#define EXT_C  45           // velocity SMEM frame (core+-2, padded)
#define IDHF   0.25f
#define DTF    4.0e-4f

// Triple-buffered global stress. Velocity lives in registers/SMEM only.
__device__ float g_syy[3][NSHOT*NS1];
__device__ float g_sxy[3][NSHOT*NS1];
__device__ float g_sxx[3][NSHOT*NS1];
__device__ float g_recs[NT*NSHOT*NREC];

__device__ __align__(128) unsigned g_flag[NBLK*32];
__device__ __align__(128) unsigned g_count = 0;
__device__ __align__(128) volatile unsigned g_phase = 0;

__device__ __forceinline__ void gbar(unsigned target)
{
    __syncthreads();
    if (threadIdx.x == 0) {
        __threadfence();
        if (atomicAdd(&g_count, 1u) == NBLK - 1) {
            g_count = 0;
            __threadfence();
            g_phase = target;
        } else {
            while ((int)(g_phase - target) < 0) { }
        }
        __threadfence();
    }
    __syncthreads();
}

__device__ __forceinline__ unsigned ld_acq(const unsigned* p)
{
    unsigned v;
    asm volatile("ld.acquire.gpu.global.u32 %0, [%1];" : "=r"(v) : "l"(p) : "memory");
    return v;
}
__device__ __forceinline__ void red_add(unsigned* p)
{
    asm volatile("red.global.add.u32 [%0], %1;" :: "l"(p), "r"(1u) : "memory");
}

__device__ __forceinline__ float pml_b(int i)
{
    const double d0 = 3.0 * 1600.0 * log(1000.0) / (2.0 * PML_W * 4.0);
    double dd = 0.0;
    if (i < PML_W) {
        double a = (double)(PML_W - i) / PML_W;
        dd = d0 * a * a;
    } else if (i >= NG - PML_W) {
        double a = ((double)i - (NG - 1 - PML_W)) / PML_W;
        dd = d0 * a * a;
    }
    return (float)exp(-dd * 4.0e-4);
}

__device__ __forceinline__ float2 ld2(const float* __restrict__ p, int idx)
{
    return *reinterpret_cast<const float2*>(p + idx);
}
__device__ __forceinline__ void st2(float* __restrict__ p, int idx, float a, float b)
{
    *reinterpret_cast<float2*>(p + idx) = make_float2(a, b);
}

__global__ __launch_bounds__(TPB, 2) void sim_kernel(
    const float* __restrict__ lamb,
    const float* __restrict__ mu,
    const float* __restrict__ buoy,
    const float* __restrict__ amps,   // [NSHOT, NSRC, NT]
    const int*   __restrict__ sloc,   // [NSHOT, NSRC, 2]
    const int*   __restrict__ rloc,   // [NSHOT, NREC, 2]
    float* __restrict__ out)          // [NSHOT, NREC, NT-1]
{
    __shared__ float s_vy[EXT_R][EXT_C];
    __shared__ float s_vx[EXT_R][EXT_C];

    const int tid  = threadIdx.x;
    const int blk  = blockIdx.x;
    const int shot = blk & 1;
    const int tile = blk >> 1;
    const int by0 = (tile / TCB) * TILE_R;
    const int bx0 = (tile % TCB) * TILE_C;
    const int base = shot * NS1;
    unsigned ph = g_phase;
    const unsigned F = g_flag[blk * 32];

    const bool has_core = (tid < 400);
    const bool has_ring = (tid >= 400 && tid < 528);
    const bool is_poller = (tid >= 528 && tid < 536);

    const int rr = has_core ? tid / 20 : 0;
    const int pp = has_core ? tid - rr * 20 : 0;
    const int cx = 2 * pp;
    const int y  = by0 + rr;
    const int x0 = bx0 + cx;
    const int o = y * NG + x0;

    // pollers: 8 same-shot torus neighbors
    int nbid = 0;
    if (is_poller) {
        const int dR[8] = {-1,-1,-1, 0, 0, 1, 1, 1};
        const int dC[8] = {-1, 0, 1,-1, 1,-1, 0, 1};
        int i = tid - 528;
        int bR = tile / TCB, bC = tile % TCB;
        int nR = (bR + dR[i] + TRB) % TRB;
        int nC = (bC + dC[i] + TCB) % TCB;
        nbid = ((nR * TCB + nC) << 1) | shot;
    }

    // ---- core wrapped global indices (float2 taps) ----
    const int ym1 = (y + NG - 1) % NG, ym2 = (y + NG - 2) % NG;
    const int yp1 = (y + 1) % NG,      yp2 = (y + 2) % NG;
    const int row  = y   * NG;
    const int rym1 = ym1 * NG, rym2 = ym2 * NG;
    const int ryp1 = yp1 * NG, ryp2 = yp2 * NG;
    const int xm2c = (x0 == 0)      ? NG - 2 : x0 - 2;
    const int xp2c = (x0 == NG - 2) ? 0      : x0 + 2;

    const float byv  = pml_b(y);
    const float bxv0 = pml_b(x0);
    const float bxv1 = pml_b(x0 + 1);
    float2 bv2 = make_float2(0,0), lam2 = make_float2(0,0), mu2 = make_float2(0,0);
    if (has_core) {
        bv2  = *reinterpret_cast<const float2*>(buoy + o);
        lam2 = *reinterpret_cast<const float2*>(lamb + o);
        mu2  = *reinterpret_cast<const float2*>(mu + o);
    }
    const float l2m0 = lam2.x + 2.0f * mu2.x;
    const float l2m1 = lam2.y + 2.0f * mu2.y;
    const bool ybord = (y < 2 || y >= NG - 2);
    const float mk0 = (ybord || x0     < 2 || x0     >= NG - 2) ? 0.0f : 1.0f;
    const float mk1 = (ybord || x0 + 1 < 2 || x0 + 1 >= NG - 2) ? 0.0f : 1.0f;
    const int svc_r = 2 + rr, svc_c = 2 + cx;

    unsigned smask = 0u;
    if (has_core) {
#pragma unroll
        for (int s = 0; s < NSRC; s++) {
            int sy = sloc[(shot*NSRC + s)*2], sx = sloc[(shot*NSRC + s)*2 + 1];
            if (sy == y && sx == x0)     smask |= 1u << s;
            if (sy == y && sx == x0 + 1) smask |= 1u << (s + 8);
        }
    }

    int rcode[8];
    int rcnt = 0;
    bool rovf = false;
    if (has_core) {
        for (int r = 0; r < NREC; r++) {
            int e = shot * NREC + r;
            int ry = rloc[e*2], rx = rloc[e*2 + 1];
            if (ry == y && (rx == x0 || rx == x0 + 1)) {
                if (rcnt < 8) rcode[rcnt++] = e * 2 + (rx - x0);
                else rovf = true;
            }
        }
    }

    // ---- ring: annulus 1..2 as 128 x-pairs on threads 400..527 ----
    int r_ty = 0, r_tx0 = 0;
    int rgrow = 0, rgrym1 = 0, rgrym2 = 0, rgryp1 = 0, rgryp2 = 0;
    int rgx0 = 0, rxm2c = 0, rxp2c = 0;
    float rbyv = 0, rbxv0 = 0, rbxv1 = 0, rbv0 = 0, rbv1 = 0, rmk0 = 0, rmk1 = 0;
    unsigned rsmask = 0u;
    if (has_ring) {
        int k = tid - 400;
        if (k < 44)       { r_ty = -2 + k / 22;        r_tx0 = -2 + 2 * (k % 22); }
        else if (k < 88)  { r_ty = 20 + (k - 44) / 22; r_tx0 = -2 + 2 * ((k - 44) % 22); }
        else if (k < 108) { r_ty = k - 88;             r_tx0 = -2; }
        else              { r_ty = k - 108;            r_tx0 = 40; }
        int gy  = (by0 + r_ty + NG) % NG;
        int gx0 = (bx0 + r_tx0 + NG) % NG;   // even; pair never straddles wrap
        rgrow  = gy * NG;
        rgrym1 = ((gy + NG - 1) % NG) * NG;
        rgrym2 = ((gy + NG - 2) % NG) * NG;
        rgryp1 = ((gy + 1) % NG) * NG;
        rgryp2 = ((gy + 2) % NG) * NG;
        rgx0  = gx0;
        rxm2c = (gx0 == 0)      ? NG - 2 : gx0 - 2;
        rxp2c = (gx0 == NG - 2) ? 0      : gx0 + 2;
        rbyv  = pml_b(gy);
        rbxv0 = pml_b(gx0);
        rbxv1 = pml_b(gx0 + 1);
        rbv0 = buoy[rgrow + gx0];
        rbv1 = buoy[rgrow + gx0 + 1];
        bool yb = (gy < 2 || gy >= NG - 2);
        rmk0 = (yb || gx0 < 2 || gx0 >= NG - 2) ? 0.0f : 1.0f;
        rmk1 = (yb || gx0 + 1 >= NG - 2 || gx0 + 1 < 2) ? 0.0f : 1.0f;
#pragma unroll
        for (int s = 0; s < NSRC; s++) {
            int sy = sloc[(shot*NSRC + s)*2], sx = sloc[(shot*NSRC + s)*2 + 1];
            if (sy == gy && sx == gx0)     rsmask |= 1u << s;
            if (sy == gy && sx == gx0 + 1) rsmask |= 1u << (s + 8);
        }
    }

    // ---- persistent register state ----
    float vy0 = 0, vy1 = 0, vx0 = 0, vx1 = 0;
    float syy0 = 0, syy1 = 0, sxy0 = 0, sxy1 = 0, sxx0 = 0, sxx1 = 0;
    float cms[8] = {0,0,0,0,0,0,0,0};   // core CPML (vel): msyyy,msxyx,msxxx,msxyy x2
    float cmv[8] = {0,0,0,0,0,0,0,0};   // core CPML (stress): mvyy,mvxx,mvyx,mvxy x2
    float r_vy0 = 0, r_vy1 = 0, r_vx0 = 0, r_vx1 = 0;
    float rms[8] = {0,0,0,0,0,0,0,0};   // ring CPML (vel) x2 cells

    // init: zero SMEM vel frame + global stress buffer 2 core
    for (int i = tid; i < EXT_R*EXT_C; i += TPB) {
        (&s_vy[0][0])[i] = 0.f;
        (&s_vx[0][0])[i] = 0.f;
    }
    if (has_core) {
        st2(g_syy[2], base + o, 0.f, 0.f);
        st2(g_sxy[2], base + o, 0.f, 0.f);
        st2(g_sxx[2], base + o, 0.f, 0.f);
    }
    __syncthreads();
    if (tid == 0) { __threadfence(); red_add(&g_flag[blk * 32]); }   // flag = F+1

    const float C1 = 1.125f;
    const float C2 = -1.0f / 24.0f;

#pragma unroll 1
    for (int t = 0; t < NT; t++) {
        const unsigned tgt = F + 1u + (unsigned)t;
        const int p = (t + 2) % 3;     // read: stress(t-1)
        const int q = t % 3;           // write: stress(t)
        const float* __restrict__ Syy = g_syy[p];
        const float* __restrict__ Sxy = g_sxy[p];
        const float* __restrict__ Sxx = g_sxx[p];

        // [A] dedicated pollers wait for neighbors; block barrier
        if (is_poller) {
            const unsigned* fp = &g_flag[nbid * 32];
            while ((int)(ld_acq(fp) - tgt) < 0) { }
        }
        __syncthreads();

        // ================= velocity: core pair (threads 0-399) =================
        if (has_core) {
            float d0, d1, m;

            float2 a_ym1 = ld2(Syy, base + rym1 + x0);
            float2 a_ym2 = ld2(Syy, base + rym2 + x0);
            float2 a_yp1 = ld2(Syy, base + ryp1 + x0);
            d0 = (C1*(syy0 - a_ym1.x) + C2*(a_yp1.x - a_ym2.x)) * IDHF;
            d1 = (C1*(syy1 - a_ym1.y) + C2*(a_yp1.y - a_ym2.y)) * IDHF;
            m = cms[0]; m = byv*m + (byv-1.0f)*d0; cms[0] = m;
            float ay0 = d0 + m;
            m = cms[4]; m = byv*m + (byv-1.0f)*d1; cms[4] = m;
            float ay1 = d1 + m;

            float2 u_xm = ld2(Sxy, base + row + xm2c);
            float2 u_xp = ld2(Sxy, base + row + xp2c);
            d0 = (C1*(sxy1 - sxy0) + C2*(u_xp.x - u_xm.y)) * IDHF;
            d1 = (C1*(u_xp.x - sxy1) + C2*(u_xp.y - sxy0)) * IDHF;
            m = cms[1]; m = bxv0*m + (bxv0-1.0f)*d0; cms[1] = m;
            ay0 += d0 + m;
            m = cms[5]; m = bxv1*m + (bxv1-1.0f)*d1; cms[5] = m;
            ay1 += d1 + m;

            vy0 += DTF * bv2.x * ay0;
            vy1 += DTF * bv2.y * ay1;

            float2 w_xm = ld2(Sxx, base + row + xm2c);
            float2 w_xp = ld2(Sxx, base + row + xp2c);
            d0 = (C1*(sxx0 - w_xm.y) + C2*(sxx1 - w_xm.x)) * IDHF;
            d1 = (C1*(sxx1 - sxx0) + C2*(w_xp.x - w_xm.y)) * IDHF;
            m = cms[2]; m = bxv0*m + (bxv0-1.0f)*d0; cms[2] = m;
            float ax0 = d0 + m;
            m = cms[6]; m = bxv1*m + (bxv1-1.0f)*d1; cms[6] = m;
            float ax1 = d1 + m;

            float2 s_yp1v = ld2(Sxy, base + ryp1 + x0);
            float2 s_yp2v = ld2(Sxy, base + ryp2 + x0);
            float2 s_ym1v = ld2(Sxy, base + rym1 + x0);
            d0 = (C1*(s_yp1v.x - sxy0) + C2*(s_yp2v.x - s_ym1v.x)) * IDHF;
            d1 = (C1*(s_yp1v.y - sxy1) + C2*(s_yp2v.y - s_ym1v.y)) * IDHF;
            m = cms[3]; m = byv*m + (byv-1.0f)*d0; cms[3] = m;
            ax0 += d0 + m;
            m = cms[7]; m = byv*m + (byv-1.0f)*d1; cms[7] = m;
            ax1 += d1 + m;

            vx0 += DTF * bv2.x * ax0;
            vx1 += DTF * bv2.y * ax1;

            if (smask) {
#pragma unroll
                for (int s = 0; s < NSRC; s++) {
                    float a = amps[(shot*NSRC + s)*NT + t];
                    if (smask & (1u << s))       vy0 += DTF * a * bv2.x;
                    if (smask & (1u << (s + 8))) vy1 += DTF * a * bv2.y;
                }
            }
            vy0 *= mk0; vy1 *= mk1;
            vx0 *= mk0; vx1 *= mk1;

            s_vy[svc_r][svc_c]   = vy0;
            s_vy[svc_r][svc_c+1] = vy1;
            s_vx[svc_r][svc_c]   = vx0;
            s_vx[svc_r][svc_c+1] = vx1;

            // receivers (own registers)
            if (rovf) {
                for (int r = 0; r < NREC; r++) {
                    int e = shot * NREC + r;
                    int ry = rloc[e*2], rx = rloc[e*2 + 1];
                    if (ry == y && (rx == x0 || rx == x0 + 1))
                        g_recs[t*(NSHOT*NREC) + e] = (rx == x0) ? vy0 : vy1;
                }
            } else {
                for (int i = 0; i < rcnt; i++) {
                    int e = rcode[i] >> 1;
                    g_recs[t*(NSHOT*NREC) + e] = (rcode[i] & 1) ? vy1 : vy0;
                }
            }
        }

        // ============ velocity: ring pair (threads 400-527, parallel) ============
        if (has_ring) {
            float d0, d1, m;

            float2 a_ym1 = ld2(Syy, base + rgrym1 + rgx0);
            float2 a_ym2 = ld2(Syy, base + rgrym2 + rgx0);
            float2 a_yp1 = ld2(Syy, base + rgryp1 + rgx0);
            float2 a_o   = ld2(Syy, base + rgrow + rgx0);
            d0 = (C1*(a_o.x - a_ym1.x) + C2*(a_yp1.x - a_ym2.x)) * IDHF;
            d1 = (C1*(a_o.y - a_ym1.y) + C2*(a_yp1.y - a_ym2.y)) * IDHF;
            m = rms[0]; m = rbyv*m + (rbyv-1.0f)*d0; rms[0] = m;
            float ay0 = d0 + m;
            m = rms[4]; m = rbyv*m + (rbyv-1.0f)*d1; rms[4] = m;
            float ay1 = d1 + m;

            float2 u_o  = ld2(Sxy, base + rgrow + rgx0);
            float2 u_xm = ld2(Sxy, base + rgrow + rxm2c);
            float2 u_xp = ld2(Sxy, base + rgrow + rxp2c);
            d0 = (C1*(u_o.y - u_o.x) + C2*(u_xp.x - u_xm.y)) * IDHF;
            d1 = (C1*(u_xp.x - u_o.y) + C2*(u_xp.y - u_o.x)) * IDHF;
            m = rms[1]; m = rbxv0*m + (rbxv0-1.0f)*d0; rms[1] = m;
            ay0 += d0 + m;
            m = rms[5]; m = rbxv1*m + (rbxv1-1.0f)*d1; rms[5] = m;
            ay1 += d1 + m;

            r_vy0 += DTF * rbv0 * ay0;
            r_vy1 += DTF * rbv1 * ay1;

            float2 w_o  = ld2(Sxx, base + rgrow + rgx0);
            float2 w_xm = ld2(Sxx, base + rgrow + rxm2c);
            float2 w_xp = ld2(Sxx, base + rgrow + rxp2c);
            d0 = (C1*(w_o.x - w_xm.y) + C2*(w_o.y - w_xm.x)) * IDHF;
            d1 = (C1*(w_o.y - w_o.x) + C2*(w_xp.x - w_xm.y)) * IDHF;
            m = rms[2]; m = rbxv0*m + (rbxv0-1.0f)*d0; rms[2] = m;
            float ax0 = d0 + m;
            m = rms[6]; m = rbxv1*m + (rbxv1-1.0f)*d1; rms[6] = m;
            float ax1 = d1 + m;

            float2 s_yp1v = ld2(Sxy, base + rgryp1 + rgx0);
            float2 s_yp2v = ld2(Sxy, base + rgryp2 + rgx0);
            float2 s_ym1v = ld2(Sxy, base + rgrym1 + rgx0);
            d0 = (C1*(s_yp1v.x - u_o.x) + C2*(s_yp2v.x - s_ym1v.x)) * IDHF;
            d1 = (C1*(s_yp1v.y - u_o.y) + C2*(s_yp2v.y - s_ym1v.y)) * IDHF;
            m = rms[3]; m = rbyv*m + (rbyv-1.0f)*d0; rms[3] = m;
            ax0 += d0 + m;
            m = rms[7]; m = rbyv*m + (rbyv-1.0f)*d1; rms[7] = m;
            ax1 += d1 + m;

            r_vx0 += DTF * rbv0 * ax0;
            r_vx1 += DTF * rbv1 * ax1;

            if (rsmask) {
#pragma unroll
                for (int s = 0; s < NSRC; s++) {
                    float a = amps[(shot*NSRC + s)*NT + t];
                    if (rsmask & (1u << s))       r_vy0 += DTF * a * rbv0;
                    if (rsmask & (1u << (s + 8))) r_vy1 += DTF * a * rbv1;
                }
            }
            r_vy0 *= rmk0; r_vy1 *= rmk1;
            r_vx0 *= rmk0; r_vx1 *= rmk1;

            s_vy[2 + r_ty][2 + r_tx0]     = r_vy0;
            s_vy[2 + r_ty][2 + r_tx0 + 1] = r_vy1;
            s_vx[2 + r_ty][2 + r_tx0]     = r_vx0;
            s_vx[2 + r_ty][2 + r_tx0 + 1] = r_vx1;
        }

        __syncthreads();   // [V] velocity frame complete

        // ================= stress: core (SMEM vel taps) =================
        if (has_core) {
            const int sy = svc_r, sx = svc_c;
            float d0, d1, m;

            d0 = (C1*(s_vy[sy+1][sx]   - vy0) + C2*(s_vy[sy+2][sx]   - s_vy[sy-1][sx])) * IDHF;
            d1 = (C1*(s_vy[sy+1][sx+1] - vy1) + C2*(s_vy[sy+2][sx+1] - s_vy[sy-1][sx+1])) * IDHF;
            m = cmv[0]; m = byv*m + (byv-1.0f)*d0; cmv[0] = m;
            float e10 = d0 + m;
            m = cmv[4]; m = byv*m + (byv-1.0f)*d1; cmv[4] = m;
            float e11 = d1 + m;

            float vxm1 = s_vx[sy][sx-1], vxm2 = s_vx[sy][sx-2];
            float vxp2 = s_vx[sy][sx+2];
            d0 = (C1*(vx0 - vxm1) + C2*(vx1 - vxm2)) * IDHF;
            d1 = (C1*(vx1 - vx0) + C2*(vxp2 - vxm1)) * IDHF;
            m = cmv[1]; m = bxv0*m + (bxv0-1.0f)*d0; cmv[1] = m;
            float e20 = d0 + m;
            m = cmv[5]; m = bxv1*m + (bxv1-1.0f)*d1; cmv[5] = m;
            float e21 = d1 + m;

            syy0 = (syy0 + DTF*(l2m0*e10 + lam2.x*e20)) * mk0;
            syy1 = (syy1 + DTF*(l2m1*e11 + lam2.y*e21)) * mk1;
            sxx0 = (sxx0 + DTF*(l2m0*e20 + lam2.x*e10)) * mk0;
            sxx1 = (sxx1 + DTF*(l2m1*e21 + lam2.y*e11)) * mk1;

            float vym1 = s_vy[sy][sx-1];
            float vyp2 = s_vy[sy][sx+2], vyp3 = s_vy[sy][sx+3];
            d0 = (C1*(vy1 - vy0) + C2*(vyp2 - vym1)) * IDHF;
            d1 = (C1*(vyp2 - vy1) + C2*(vyp3 - vy0)) * IDHF;
            m = cmv[2]; m = bxv0*m + (bxv0-1.0f)*d0; cmv[2] = m;
            float g0 = d0 + m;
            m = cmv[6]; m = bxv1*m + (bxv1-1.0f)*d1; cmv[6] = m;
            float g1 = d1 + m;

            d0 = (C1*(vx0 - s_vx[sy-1][sx])   + C2*(s_vx[sy+1][sx]   - s_vx[sy-2][sx])) * IDHF;
            d1 = (C1*(vx1 - s_vx[sy-1][sx+1]) + C2*(s_vx[sy+1][sx+1] - s_vx[sy-2][sx+1])) * IDHF;
            m = cmv[3]; m = byv*m + (byv-1.0f)*d0; cmv[3] = m;
            g0 += d0 + m;
            m = cmv[7]; m = byv*m + (byv-1.0f)*d1; cmv[7] = m;
            g1 += d1 + m;

            sxy0 = (sxy0 + DTF*mu2.x*g0) * mk0;
            sxy1 = (sxy1 + DTF*mu2.y*g1) * mk1;

            st2(g_syy[q], base + o, syy0, syy1);
            st2(g_sxy[q], base + o, sxy0, sxy1);
            st2(g_sxx[q], base + o, sxx0, sxx1);
        }

        // [S] publish step t
        __syncthreads();
        if (tid == 0) { __threadfence(); red_add(&g_flag[blk * 32]); }
    }

    // ---------------- finalize (needs all blocks' g_recs) ----------------
    gbar(ph + 1);
    const int gtid = blk * TPB + tid;
    const int total = NSHOT * NREC * (NT - 1);
    if (gtid < total) {
        int t = gtid % (NT - 1);
        int e = gtid / (NT - 1);
        out[e * (NT - 1) + t] = 0.5f * (g_recs[(t + 1)*(NSHOT*NREC) + e]
                                      + g_recs[t      *(NSHOT*NREC) + e]);
    }
}

extern "C" void kernel_launch(void* const* d_in, const int* in_sizes, int n_in,
                              void* d_out, int out_size)
{
    const float* lamb = (const float*)d_in[0];
    const float* mu   = (const float*)d_in[1];
    const float* buoy = (const float*)d_in[2];
    const float* amps = (const float*)d_in[3];
    const int*   sloc = (const int*)d_in[4];
    const int*   rloc = (const int*)d_in[5];
    float* out = (float*)d_out;

    sim_kernel<<<NBLK, TPB>>>(lamb, mu, buoy, amps, sloc, rloc, out);
}

// round 17
// speedup vs baseline: 1.2062x; 1.2062x over previous
#include <cuda_runtime.h>
#include <math.h>

#define NG     320
#define NS1    (NG*NG)
#define NSHOT  2
#define NSRC   8
#define NREC   96
#define NT     160
#define PML_W  20
#define NBLK   256          // 128 tiles x 2 shots
#define TPB    400
#define TILE_R 20
#define TILE_C 40
#define TCB    8
#define TRB    16
#define NRING  240
#define EXT_R  24
#define EXT_C  45           // 44 used + 1 pad
#define IDHF   0.25f
#define DTF    4.0e-4f

// Triple-buffered global stress. Velocity lives only in registers/SMEM.
__device__ float g_syy[3][NSHOT*NS1];
__device__ float g_sxy[3][NSHOT*NS1];
__device__ float g_sxx[3][NSHOT*NS1];
__device__ float g_recs[NT*NSHOT*NREC];

// per-block step flags, one 128B line each; monotonic across graph replays
__device__ __align__(128) unsigned g_flag[NBLK*32];
__device__ __align__(128) unsigned g_count = 0;
__device__ __align__(128) volatile unsigned g_phase = 0;

// one-shot global barrier (used only before finalize)
__device__ __forceinline__ void gbar(unsigned target)
{
    __syncthreads();
    if (threadIdx.x == 0) {
        __threadfence();
        if (atomicAdd(&g_count, 1u) == NBLK - 1) {
            g_count = 0;
            __threadfence();
            g_phase = target;
        } else {
            while ((int)(g_phase - target) < 0) { }
        }
        __threadfence();
    }
    __syncthreads();
}

__device__ __forceinline__ unsigned ld_acq(const unsigned* p)
{
    unsigned v;
    asm volatile("ld.acquire.gpu.global.u32 %0, [%1];" : "=r"(v) : "l"(p) : "memory");
    return v;
}
// release-annotated fire-and-forget add: orders ALL prior writes (STS+STG)
// before the flag increment becomes visible; pairs with ld.acquire polls.
__device__ __forceinline__ void red_release_add(unsigned* p)
{
    asm volatile("red.release.gpu.global.add.u32 [%0], %1;" :: "l"(p), "r"(1u) : "memory");
}

__device__ __forceinline__ float pml_b(int i)
{
    const double d0 = 3.0 * 1600.0 * log(1000.0) / (2.0 * PML_W * 4.0);
    double dd = 0.0;
    if (i < PML_W) {
        double a = (double)(PML_W - i) / PML_W;
        dd = d0 * a * a;
    } else if (i >= NG - PML_W) {
        double a = ((double)i - (NG - 1 - PML_W)) / PML_W;
        dd = d0 * a * a;
    }
    return (float)exp(-dd * 4.0e-4);
}

__device__ __forceinline__ float2 ld2(const float* __restrict__ p, int idx)
{
    return *reinterpret_cast<const float2*>(p + idx);
}
__device__ __forceinline__ void st2(float* __restrict__ p, int idx, float a, float b)
{
    *reinterpret_cast<float2*>(p + idx) = make_float2(a, b);
}

__global__ __launch_bounds__(TPB, 2) void sim_kernel(
    const float* __restrict__ lamb,
    const float* __restrict__ mu,
    const float* __restrict__ buoy,
    const float* __restrict__ amps,   // [NSHOT, NSRC, NT]
    const int*   __restrict__ sloc,   // [NSHOT, NSRC, 2]
    const int*   __restrict__ rloc,   // [NSHOT, NREC, 2]
    float* __restrict__ out)          // [NSHOT, NREC, NT-1]
{
    __shared__ float s_vy[EXT_R][EXT_C];
    __shared__ float s_vx[EXT_R][EXT_C];

    const int tid  = threadIdx.x;
    const int blk  = blockIdx.x;
    const int shot = blk & 1;
    const int tile = blk >> 1;
    const int by0 = (tile / TCB) * TILE_R;
    const int bx0 = (tile % TCB) * TILE_C;
    const int rr = tid / 20;
    const int pp = tid - rr * 20;
    const int cx = 2 * pp;
    const int y  = by0 + rr;
    const int x0 = bx0 + cx;
    const int base = shot * NS1;
    const int o = y * NG + x0;
    unsigned ph = g_phase;
    const unsigned F = g_flag[blk * 32];

    // 8 same-shot torus neighbors, polled by tid 0..7 (warp 0 = poll+core only)
    int nbid = 0;
    if (tid < 8) {
        const int dR[8] = {-1,-1,-1, 0, 0, 1, 1, 1};
        const int dC[8] = {-1, 0, 1,-1, 1,-1, 0, 1};
        int bR = tile / TCB, bC = tile % TCB;
        int nR = (bR + dR[tid] + TRB) % TRB;
        int nC = (bC + dC[tid] + TCB) % TCB;
        nbid = ((nR * TCB + nC) << 1) | shot;
    }

    // ---- core wrapped indices ----
    const int ym1 = (y + NG - 1) % NG, ym2 = (y + NG - 2) % NG;
    const int yp1 = (y + 1) % NG,      yp2 = (y + 2) % NG;
    const int row  = y   * NG;
    const int rym1 = ym1 * NG, rym2 = ym2 * NG;
    const int ryp1 = yp1 * NG, ryp2 = yp2 * NG;
    const int xm2c = (x0 == 0)      ? NG - 2 : x0 - 2;
    const int xp2c = (x0 == NG - 2) ? 0      : x0 + 2;

    const float byv  = pml_b(y);
    const float bxv0 = pml_b(x0);
    const float bxv1 = pml_b(x0 + 1);
    const float2 bv2  = ld2(buoy, o);
    const float2 lam2 = ld2(lamb, o);
    const float2 mu2  = ld2(mu,   o);
    const float l2m0 = lam2.x + 2.0f * mu2.x;
    const float l2m1 = lam2.y + 2.0f * mu2.y;
    const bool ybord = (y < 2 || y >= NG - 2);
    const float mk0 = (ybord || x0     < 2 || x0     >= NG - 2) ? 0.0f : 1.0f;
    const float mk1 = (ybord || x0 + 1 < 2 || x0 + 1 >= NG - 2) ? 0.0f : 1.0f;

    unsigned smask = 0u;
#pragma unroll
    for (int s = 0; s < NSRC; s++) {
        int sy = sloc[(shot*NSRC + s)*2], sx = sloc[(shot*NSRC + s)*2 + 1];
        if (sy == y && sx == x0)     smask |= 1u << s;
        if (sy == y && sx == x0 + 1) smask |= 1u << (s + 8);
    }

    int rcode[8];
    int rcnt = 0;
    bool rovf = false;
    for (int r = 0; r < NREC; r++) {
        int e = shot * NREC + r;
        int ry = rloc[e*2], rx = rloc[e*2 + 1];
        if (ry == y && (rx == x0 || rx == x0 + 1)) {
            if (rcnt < 8) rcode[rcnt++] = e * 2 + (rx - x0);
            else rovf = true;
        }
    }

    // ---- ring cells on threads 160..399 (poller warp 0 carries none) ----
    const bool has_ring = (tid >= 160);
    int r_ey = 0, r_ex = 0, r_gy = 0, r_gx = 0;
    if (has_ring) {
        int k = tid - 160;
        if (k < 80)       { r_ey = k / 40;              r_ex = 2 + (k % 40); }
        else if (k < 160) { r_ey = 22 + (k - 80) / 40;  r_ex = 2 + ((k - 80) % 40); }
        else if (k < 200) { r_ey = 2 + (k - 160) % 20;  r_ex = (k - 160) / 20; }
        else              { r_ey = 2 + (k - 200) % 20;  r_ex = 42 + (k - 200) / 20; }
        r_gy = (by0 + r_ey - 2 + NG) % NG;
        r_gx = (bx0 + r_ex - 2 + NG) % NG;
    }
    const int gro   = r_gy * NG;
    const int grym1 = ((r_gy + NG - 1) % NG) * NG;
    const int grym2 = ((r_gy + NG - 2) % NG) * NG;
    const int gryp1 = ((r_gy + 1) % NG) * NG;
    const int gryp2 = ((r_gy + 2) % NG) * NG;
    const int gxm1 = (r_gx + NG - 1) % NG, gxm2 = (r_gx + NG - 2) % NG;
    const int gxp1 = (r_gx + 1) % NG,      gxp2 = (r_gx + 2) % NG;
    const int ro = gro + r_gx;
    const float rbyv = pml_b(r_gy);
    const float rbxv = pml_b(r_gx);
    const float rbv  = buoy[ro];
    const float rmk  = (r_gy < 2 || r_gy >= NG-2 || r_gx < 2 || r_gx >= NG-2) ? 0.0f : 1.0f;
    unsigned rsmask = 0u;
    if (has_ring) {
#pragma unroll
        for (int s = 0; s < NSRC; s++)
            if (sloc[(shot*NSRC + s)*2] == r_gy && sloc[(shot*NSRC + s)*2 + 1] == r_gx)
                rsmask |= 1u << s;
    }

    // ---- register state (single shot, 2 cells) ----
    float vy[2]  = {0,0}, vx[2]  = {0,0};
    float syy[2] = {0,0}, sxy[2] = {0,0}, sxx[2] = {0,0};
    float m_vyy[2]  = {0,0}, m_vyx[2]  = {0,0};
    float m_vxy[2]  = {0,0}, m_vxx[2]  = {0,0};
    float m_syyy[2] = {0,0}, m_sxyy[2] = {0,0};
    float m_sxyx[2] = {0,0}, m_sxxx[2] = {0,0};
    float r_vy = 0, r_vx = 0;
    float r_msyyy = 0, r_msxyy = 0, r_msxyx = 0, r_msxxx = 0;

    // zero stress buffer 2 on own core: read as str(-1) by step 0
    {
        int i = base + o;
        st2(g_syy[2], i, 0.f, 0.f);
        st2(g_sxy[2], i, 0.f, 0.f);
        st2(g_sxx[2], i, 0.f, 0.f);
    }
    __syncthreads();
    if (tid == 0) red_release_add(&g_flag[blk * 32]);   // flag = F+1

    const float C1 = 1.125f;
    const float C2 = -1.0f / 24.0f;

#pragma unroll 1
    for (int t = 0; t < NT; t++) {
        // wait for 8 same-shot neighbors to have completed step t-1
        if (tid < 8) {
            const unsigned tgt = F + 1u + (unsigned)t;
            const unsigned* fp = &g_flag[nbid * 32];
            while ((int)(ld_acq(fp) - tgt) < 0) { }
        }
        __syncthreads();

        const int p = (t + 2) % 3;     // read buffer: str(t-1)
        const int q = t % 3;           // write buffer: str(t)
        const float* __restrict__ Syy = g_syy[p];
        const float* __restrict__ Sxy = g_sxy[p];
        const float* __restrict__ Sxx = g_sxx[p];

        // ================= velocity: core =================
        {
            float d0, d1, m;

            float2 a_ym1 = ld2(Syy, base + rym1 + x0);
            float2 a_ym2 = ld2(Syy, base + rym2 + x0);
            float2 a_yp1 = ld2(Syy, base + ryp1 + x0);
            d0 = (C1*(syy[0] - a_ym1.x) + C2*(a_yp1.x - a_ym2.x)) * IDHF;
            d1 = (C1*(syy[1] - a_ym1.y) + C2*(a_yp1.y - a_ym2.y)) * IDHF;
            m = m_syyy[0]; m = byv*m + (byv-1.0f)*d0; m_syyy[0] = m;
            float ay0 = d0 + m;
            m = m_syyy[1]; m = byv*m + (byv-1.0f)*d1; m_syyy[1] = m;
            float ay1 = d1 + m;

            float2 u_xm = ld2(Sxy, base + row + xm2c);
            float2 u_xp = ld2(Sxy, base + row + xp2c);
            d0 = (C1*(sxy[1] - sxy[0]) + C2*(u_xp.x - u_xm.y)) * IDHF;
            d1 = (C1*(u_xp.x - sxy[1]) + C2*(u_xp.y - sxy[0])) * IDHF;
            m = m_sxyx[0]; m = bxv0*m + (bxv0-1.0f)*d0; m_sxyx[0] = m;
            ay0 += d0 + m;
            m = m_sxyx[1]; m = bxv1*m + (bxv1-1.0f)*d1; m_sxyx[1] = m;
            ay1 += d1 + m;

            vy[0] += DTF * bv2.x * ay0;
            vy[1] += DTF * bv2.y * ay1;

            float2 w_xm = ld2(Sxx, base + row + xm2c);
            float2 w_xp = ld2(Sxx, base + row + xp2c);
            d0 = (C1*(sxx[0] - w_xm.y) + C2*(sxx[1] - w_xm.x)) * IDHF;
            d1 = (C1*(sxx[1] - sxx[0]) + C2*(w_xp.x - w_xm.y)) * IDHF;
            m = m_sxxx[0]; m = bxv0*m + (bxv0-1.0f)*d0; m_sxxx[0] = m;
            float ax0 = d0 + m;
            m = m_sxxx[1]; m = bxv1*m + (bxv1-1.0f)*d1; m_sxxx[1] = m;
            float ax1 = d1 + m;

            float2 s_yp1v = ld2(Sxy, base + ryp1 + x0);
            float2 s_yp2v = ld2(Sxy, base + ryp2 + x0);
            float2 s_ym1v = ld2(Sxy, base + rym1 + x0);
            d0 = (C1*(s_yp1v.x - sxy[0]) + C2*(s_yp2v.x - s_ym1v.x)) * IDHF;
            d1 = (C1*(s_yp1v.y - sxy[1]) + C2*(s_yp2v.y - s_ym1v.y)) * IDHF;
            m = m_sxyy[0]; m = byv*m + (byv-1.0f)*d0; m_sxyy[0] = m;
            ax0 += d0 + m;
            m = m_sxyy[1]; m = byv*m + (byv-1.0f)*d1; m_sxyy[1] = m;
            ax1 += d1 + m;

            vx[0] += DTF * bv2.x * ax0;
            vx[1] += DTF * bv2.y * ax1;

            if (smask) {
#pragma unroll
                for (int s = 0; s < NSRC; s++) {
                    if (smask & (1u << s))
                        vy[0] += DTF * amps[(shot*NSRC + s)*NT + t] * bv2.x;
                    if (smask & (1u << (s + 8)))
                        vy[1] += DTF * amps[(shot*NSRC + s)*NT + t] * bv2.y;
                }
            }
            vy[0] *= mk0; vy[1] *= mk1;
            vx[0] *= mk0; vx[1] *= mk1;

            s_vy[2+rr][2+cx]   = vy[0];
            s_vy[2+rr][2+cx+1] = vy[1];
            s_vx[2+rr][2+cx]   = vx[0];
            s_vx[2+rr][2+cx+1] = vx[1];
        }

        // ================= velocity: ring =================
        if (has_ring) {
            float d, m;

            d = (C1*(Syy[base+ro] - Syy[base+grym1+r_gx])
               + C2*(Syy[base+gryp1+r_gx] - Syy[base+grym2+r_gx])) * IDHF;
            m = r_msyyy; m = rbyv*m + (rbyv-1.0f)*d; r_msyyy = m;
            float ay = d + m;

            d = (C1*(Sxy[base+gro+gxp1] - Sxy[base+ro])
               + C2*(Sxy[base+gro+gxp2] - Sxy[base+gro+gxm1])) * IDHF;
            m = r_msxyx; m = rbxv*m + (rbxv-1.0f)*d; r_msxyx = m;
            ay += d + m;

            r_vy += DTF * rbv * ay;

            d = (C1*(Sxx[base+ro] - Sxx[base+gro+gxm1])
               + C2*(Sxx[base+gro+gxp1] - Sxx[base+gro+gxm2])) * IDHF;
            m = r_msxxx; m = rbxv*m + (rbxv-1.0f)*d; r_msxxx = m;
            float ax = d + m;

            d = (C1*(Sxy[base+gryp1+r_gx] - Sxy[base+ro])
               + C2*(Sxy[base+gryp2+r_gx] - Sxy[base+grym1+r_gx])) * IDHF;
            m = r_msxyy; m = rbyv*m + (rbyv-1.0f)*d; r_msxyy = m;
            ax += d + m;

            r_vx += DTF * rbv * ax;

            if (rsmask) {
#pragma unroll
                for (int s = 0; s < NSRC; s++)
                    if (rsmask & (1u << s))
                        r_vy += DTF * amps[(shot*NSRC + s)*NT + t] * rbv;
            }
            r_vy *= rmk;
            r_vx *= rmk;
            s_vy[r_ey][r_ex] = r_vy;
            s_vx[r_ey][r_ex] = r_vx;
        }

        // receivers (own registers)
        if (rovf) {
            for (int r = 0; r < NREC; r++) {
                int e = shot * NREC + r;
                int ry = rloc[e*2], rx = rloc[e*2 + 1];
                if (ry == y && (rx == x0 || rx == x0 + 1))
                    g_recs[t*(NSHOT*NREC) + e] = vy[rx - x0];
            }
        } else {
            for (int i = 0; i < rcnt; i++) {
                int e = rcode[i] >> 1, c = rcode[i] & 1;
                g_recs[t*(NSHOT*NREC) + e] = vy[c];
            }
        }

        __syncthreads();

        // ================= stress: core (SMEM taps) =================
        {
            const int sy = 2 + rr, sx = 2 + cx;
            float d0, d1, m;

            d0 = (C1*(s_vy[sy+1][sx]   - vy[0])
                + C2*(s_vy[sy+2][sx]   - s_vy[sy-1][sx])) * IDHF;
            d1 = (C1*(s_vy[sy+1][sx+1] - vy[1])
                + C2*(s_vy[sy+2][sx+1] - s_vy[sy-1][sx+1])) * IDHF;
            m = m_vyy[0]; m = byv*m + (byv-1.0f)*d0; m_vyy[0] = m;
            float e10 = d0 + m;
            m = m_vyy[1]; m = byv*m + (byv-1.0f)*d1; m_vyy[1] = m;
            float e11 = d1 + m;

            float vxm1 = s_vx[sy][sx-1], vxm2 = s_vx[sy][sx-2];
            float vxp2 = s_vx[sy][sx+2];
            d0 = (C1*(vx[0] - vxm1) + C2*(vx[1] - vxm2)) * IDHF;
            d1 = (C1*(vx[1] - vx[0]) + C2*(vxp2 - vxm1)) * IDHF;
            m = m_vxx[0]; m = bxv0*m + (bxv0-1.0f)*d0; m_vxx[0] = m;
            float e20 = d0 + m;
            m = m_vxx[1]; m = bxv1*m + (bxv1-1.0f)*d1; m_vxx[1] = m;
            float e21 = d1 + m;

            syy[0] = (syy[0] + DTF*(l2m0*e10 + lam2.x*e20)) * mk0;
            syy[1] = (syy[1] + DTF*(l2m1*e11 + lam2.y*e21)) * mk1;
            sxx[0] = (sxx[0] + DTF*(l2m0*e20 + lam2.x*e10)) * mk0;
            sxx[1] = (sxx[1] + DTF*(l2m1*e21 + lam2.y*e11)) * mk1;

            float vym1 = s_vy[sy][sx-1];
            float vyp2 = s_vy[sy][sx+2], vyp3 = s_vy[sy][sx+3];
            d0 = (C1*(vy[1] - vy[0]) + C2*(vyp2 - vym1)) * IDHF;
            d1 = (C1*(vyp2 - vy[1]) + C2*(vyp3 - vy[0])) * IDHF;
            m = m_vyx[0]; m = bxv0*m + (bxv0-1.0f)*d0; m_vyx[0] = m;
            float g0 = d0 + m;
            m = m_vyx[1]; m = bxv1*m + (bxv1-1.0f)*d1; m_vyx[1] = m;
            float g1 = d1 + m;

            d0 = (C1*(vx[0] - s_vx[sy-1][sx])
                + C2*(s_vx[sy+1][sx] - s_vx[sy-2][sx])) * IDHF;
            d1 = (C1*(vx[1] - s_vx[sy-1][sx+1])
                + C2*(s_vx[sy+1][sx+1] - s_vx[sy-2][sx+1])) * IDHF;
            m = m_vxy[0]; m = byv*m + (byv-1.0f)*d0; m_vxy[0] = m;
            g0 += d0 + m;
            m = m_vxy[1]; m = byv*m + (byv-1.0f)*d1; m_vxy[1] = m;
            g1 += d1 + m;

            sxy[0] = (sxy[0] + DTF*mu2.x*g0) * mk0;
            sxy[1] = (sxy[1] + DTF*mu2.y*g1) * mk1;

            st2(g_syy[q], base + o, syy[0], syy[1]);
            st2(g_sxy[q], base + o, sxy[0], sxy[1]);
            st2(g_sxx[q], base + o, sxx[0], sxx[1]);
        }

        // publish step t (release-annotated: no separate membar on the chain)
        __syncthreads();
        if (tid == 0) red_release_add(&g_flag[blk * 32]);
    }

    // ---------------- finalize (needs all blocks' g_recs) ----------------
    gbar(ph + 1);
    const int gtid = blk * TPB + tid;
    const int total = NSHOT * NREC * (NT - 1);
    if (gtid < total) {
        int t = gtid % (NT - 1);
        int e = gtid / (NT - 1);
        out[e * (NT - 1) + t] = 0.5f * (g_recs[(t + 1)*(NSHOT*NREC) + e]
                                      + g_recs[t      *(NSHOT*NREC) + e]);
    }
}

extern "C" void kernel_launch(void* const* d_in, const int* in_sizes, int n_in,
                              void* d_out, int out_size)
{
    const float* lamb = (const float*)d_in[0];
    const float* mu   = (const float*)d_in[1];
    const float* buoy = (const float*)d_in[2];
    const float* amps = (const float*)d_in[3];
    const int*   sloc = (const int*)d_in[4];
    const int*   rloc = (const int*)d_in[5];
    float* out = (float*)d_out;

    sim_kernel<<<NBLK, TPB>>>(lamb, mu, buoy, amps, sloc, rloc, out);
}